// round 15
// baseline (speedup 1.0000x reference)
#include <cuda_runtime.h>
#include <cuda_bf16.h>
#include <cuda_fp16.h>
#include <cstdint>

#define F      128
#define H      128
#define DEG    16
#define KDIM   256
#define NMAX   131072
#define BMAX   16384
#define PITCH  136            // fp16/row (K=128); 272 B ≡ 4 words (mod 32) -> conflict-free
#define ROWB   272
#define HSLAB  (64 * ROWB)    // 17408 B  (64-row A slab)
#define SLAB   (128 * ROWB)   // 34816 B  (128-n B slab)
// gemm1b smem: A[buf2] + B[1]
#define SMEM_G1 (2 * HSLAB + SLAB)    // 69632 B -> 2 CTAs/SM
// agg1f smem: A[64] + B(w1_top) + Yt[64 rows x 256 B]
#define AG_A    0
#define AG_B    HSLAB
#define AG_YT   (HSLAB + SLAB)        // 52224
#define SMEM_AG (AG_YT + 64 * 256)    // 68608 B -> 2 CTAs/SM

#define PITCH2 264            // fp16/row gemm2 (K=256); 528 B ≡ 4 words (mod 32)
#define ROWB2  528
#define A2SLAB (64 * ROWB2)   // 33792 B
#define B2SLAB (128 * ROWB2)  // 67584 B per lvl
#define SMEM_G2 (A2SLAB + 2 * B2SLAB)  // 168960 B

// ---------------- scratch (fp16; Yb/h1/x2 in PERMUTED col layout) ----------------
__device__ __half g_Yb[(size_t)NMAX * 128];     // f @ w1_bot (gathered)
__device__ __half g_h1[(size_t)NMAX * 128];     // layer-1 embeddings
__device__ __half g_B1img[2][128 * PITCH];      // [ch][n][k]   (w1 fp16; ch0=top, ch1=bot)
__device__ __half g_B2img[2][128 * PITCH2];     // [lvl][n][p]  (w2 hi/lo fp16, k-rows permuted)
__device__ __half g_x2[(size_t)BMAX * 256];     // layer2 input (fp16)

// ---------------- PTX helpers ----------------
__device__ __forceinline__ void mma16816h(float* c, const uint32_t* a, const uint32_t* b) {
    asm volatile(
        "mma.sync.aligned.m16n8k16.row.col.f32.f16.f16.f32 "
        "{%0,%1,%2,%3}, {%4,%5,%6,%7}, {%8,%9}, {%0,%1,%2,%3};"
        : "+f"(c[0]), "+f"(c[1]), "+f"(c[2]), "+f"(c[3])
        : "r"(a[0]), "r"(a[1]), "r"(a[2]), "r"(a[3]), "r"(b[0]), "r"(b[1]));
}
__device__ __forceinline__ void ldsm4(uint32_t* r, uint32_t addr) {
    asm volatile("ldmatrix.sync.aligned.m8n8.x4.shared.b16 {%0,%1,%2,%3}, [%4];"
        : "=r"(r[0]), "=r"(r[1]), "=r"(r[2]), "=r"(r[3]) : "r"(addr));
}
__device__ __forceinline__ uint32_t smem_u32(const void* p) {
    return (uint32_t)__cvta_generic_to_shared(p);
}
__device__ __forceinline__ void split_fp16(float v, __half& hi, __half& lo) {
    hi = __float2half_rn(v);
    lo = __float2half_rn(v - __half2float(hi));
}
__device__ __forceinline__ uint32_t h2bits(__half2 h) {
    return *reinterpret_cast<uint32_t*>(&h);
}
__device__ __forceinline__ void pdl_wait() {
    asm volatile("griddepcontrol.wait;" ::: "memory");
}
__device__ __forceinline__ void pdl_trigger() {
    asm volatile("griddepcontrol.launch_dependents;" :::);
}
__device__ __forceinline__ void acc8(float* a, uint4 u) {
    float2 p0 = __half22float2(*reinterpret_cast<__half2*>(&u.x));
    float2 p1 = __half22float2(*reinterpret_cast<__half2*>(&u.y));
    float2 p2 = __half22float2(*reinterpret_cast<__half2*>(&u.z));
    float2 p3 = __half22float2(*reinterpret_cast<__half2*>(&u.w));
    a[0] += p0.x; a[1] += p0.y; a[2] += p1.x; a[3] += p1.y;
    a[4] += p2.x; a[5] += p2.y; a[6] += p3.x; a[7] += p3.y;
}

// ---------------- kernel 1: build fp16 weight images ----------------
__global__ void prep_kernel(const float* __restrict__ w1, const float* __restrict__ w2) {
    int i = blockIdx.x * 256 + threadIdx.x;          // 65536 total
    if (i < 32768) {
        int ch = i >> 14, n = (i >> 7) & 127, k = i & 127;
        float v = w1[(size_t)(ch * 128 + k) * 128 + n];
        g_B1img[ch][n * PITCH + k] = __float2half_rn(v);
    } else if (i < 65536) {
        int j = i - 32768;
        int n = j & 127, p = j >> 7;                 // p = storage k-index 0..255
        int p1  = p & 127;
        int sig = (p1 & 64) + ((p1 >> 1) & 7) * 8 + ((p1 >> 4) & 3) * 2 + (p1 & 1);
        int k   = (p & 128) + sig;
        float v = w2[(size_t)k * 128 + n];
        __half hb, lb;
        split_fp16(v, hb, lb);
        g_B2img[0][n * PITCH2 + p] = hb;
        g_B2img[1][n * PITCH2 + p] = lb;
    }
    pdl_trigger();
}

// ---------------- kernel 2: gemm1b  Yb[N,128] = f16(f) @ f16(w1_bot), permuted cols ----------------
// warps: warp_m (2 x 32 rows) x warp_n (4 x 32 logical cols)
__global__ void __launch_bounds__(256, 2) gemm1b_kernel(
    const float* __restrict__ f, __half* __restrict__ Yb, int nRows, int nHT)
{
    extern __shared__ unsigned char smem[];
    const int tid = threadIdx.x, wid = tid >> 5, lid = tid & 31;
    const int g   = lid >> 2, tig = lid & 3;
    const int warp_m = wid & 1, warp_n = wid >> 1;
    const uint32_t smem_base = smem_u32(smem);

    const int offA = ((lid & 7) + ((lid >> 3) & 1) * 8) * ROWB + (lid >> 4) * 16;
    const int offB = ((lid & 7) + (lid >> 4) * 8) * ROWB + ((lid >> 3) & 1) * 16;

    const int r_st = tid >> 5;
    const int k_st = (tid & 31) * 4;

    float4 Rst[8];
    auto LOADHT = [&](int ht) {
        const int base = ht * 64;
        #pragma unroll
        for (int j = 0; j < 8; j++) {
            int grow = base + j * 8 + r_st;
            Rst[j] = (grow < nRows) ? *(const float4*)(f + (size_t)grow * 128 + k_st)
                                    : make_float4(0.f, 0.f, 0.f, 0.f);
        }
    };
    auto STOREHT = [&](int buf) {
        unsigned char* Ah = smem + buf * HSLAB;
        #pragma unroll
        for (int j = 0; j < 8; j++) {
            uint2 u;
            u.x = h2bits(__floats2half2_rn(Rst[j].x, Rst[j].y));
            u.y = h2bits(__floats2half2_rn(Rst[j].z, Rst[j].w));
            int r = j * 8 + r_st;
            *(uint2*)(Ah + r * ROWB + k_st * 2) = u;
        }
    };

    int cur = 0;
    int ht = blockIdx.x;
    if (ht < nHT) { LOADHT(ht); STOREHT(0); }

    pdl_wait();   // w1_bot image ready
    {
        const uint4* src = (const uint4*)&g_B1img[1][0];
        uint4* dst = (uint4*)(smem + 2 * HSLAB);
        #pragma unroll 4
        for (int i = tid; i < SLAB / 16; i += 256) dst[i] = src[i];
    }
    __syncthreads();

    const int colbase = 64 * (warp_n >> 1) + tig * 16 + 8 * (warp_n & 1);

    while (ht < nHT) {
        const int htn  = ht + gridDim.x;
        const int base = ht * 64;

        if (htn < nHT) LOADHT(htn);

        float acc[2][4][4];
        #pragma unroll
        for (int mb = 0; mb < 2; mb++)
            #pragma unroll
            for (int nb = 0; nb < 4; nb++)
                #pragma unroll
                for (int q = 0; q < 4; q++) acc[mb][nb][q] = 0.f;

        const uint32_t Abase = smem_base + cur * HSLAB + warp_m * 32 * ROWB + offA;
        const uint32_t Bbase = smem_base + 2 * HSLAB + warp_n * 32 * ROWB + offB;
        #pragma unroll
        for (int ks = 0; ks < 8; ks++) {
            const int kB = ks * 32;
            uint32_t a[2][4];
            ldsm4(a[0], Abase + kB);
            ldsm4(a[1], Abase + 16 * ROWB + kB);
            uint32_t b[2][4];
            ldsm4(b[0], Bbase + kB);
            ldsm4(b[1], Bbase + 16 * ROWB + kB);
            #pragma unroll
            for (int mb = 0; mb < 2; mb++)
                #pragma unroll
                for (int pr = 0; pr < 2; pr++) {
                    mma16816h(acc[mb][pr * 2],     a[mb], &b[pr][0]);
                    mma16816h(acc[mb][pr * 2 + 1], a[mb], &b[pr][2]);
                }
        }

        // permuted epilogue: 8 contiguous halfs -> 1x STG.128 per (mb, half)
        #pragma unroll
        for (int mb = 0; mb < 2; mb++) {
            int row0 = base + warp_m * 32 + mb * 16 + g;
            #pragma unroll
            for (int half = 0; half < 2; half++) {
                int r = row0 + half * 8;
                if (r < nRows) {
                    uint4 v = make_uint4(
                        h2bits(__floats2half2_rn(acc[mb][0][half*2], acc[mb][0][half*2+1])),
                        h2bits(__floats2half2_rn(acc[mb][1][half*2], acc[mb][1][half*2+1])),
                        h2bits(__floats2half2_rn(acc[mb][2][half*2], acc[mb][2][half*2+1])),
                        h2bits(__floats2half2_rn(acc[mb][3][half*2], acc[mb][3][half*2+1])));
                    *(uint4*)(Yb + (size_t)r * 128 + colbase) = v;
                }
            }
        }

        if (htn < nHT) STOREHT(cur ^ 1);
        __syncthreads();
        cur ^= 1;
        ht = htn;
    }
    pdl_trigger();
}

// ---------------- kernel 3: agg1f — fused Yt-GEMM + gather-mean ----------------
// Block = 64 nodes. Phase 1 (pre-wait): stage f rows + w1_top, MMA -> Yt smem (σ layout).
// Phase 2 (post-wait): h1 = f16(Yt_smem + mean(Yb[nbr])).
__global__ void __launch_bounds__(256, 2) agg1f_kernel(
    const float* __restrict__ f, const __half* __restrict__ Yb,
    const int* __restrict__ nbr, __half* __restrict__ h1, int N)
{
    extern __shared__ unsigned char smem[];
    const int tid = threadIdx.x, wid = tid >> 5, lid = tid & 31;
    const int g   = lid >> 2, tig = lid & 3;
    const uint32_t smem_base = smem_u32(smem);
    const int base = blockIdx.x * 64;

    // ---- phase 1a: stage A (f rows, fp32 -> fp16) ----
    {
        const int r_st = tid >> 5, k_st = (tid & 31) * 4;
        #pragma unroll
        for (int j = 0; j < 8; j++) {
            int grow = base + j * 8 + r_st;
            float4 v = (grow < N) ? *(const float4*)(f + (size_t)grow * 128 + k_st)
                                  : make_float4(0.f, 0.f, 0.f, 0.f);
            uint2 u;
            u.x = h2bits(__floats2half2_rn(v.x, v.y));
            u.y = h2bits(__floats2half2_rn(v.z, v.w));
            *(uint2*)(smem + AG_A + (j * 8 + r_st) * ROWB + k_st * 2) = u;
        }
    }
    // ---- phase 1b: stage B (w1_top image) ----
    {
        const uint4* src = (const uint4*)&g_B1img[0][0];
        uint4* dst = (uint4*)(smem + AG_B);
        #pragma unroll 4
        for (int i = tid; i < SLAB / 16; i += 256) dst[i] = src[i];
    }
    __syncthreads();

    // ---- phase 1c: MMA  Yt[64,128]; warp w covers logical cols [16w, 16w+16) ----
    {
        const int offA = ((lid & 7) + ((lid >> 3) & 1) * 8) * ROWB + (lid >> 4) * 16;
        const int offB = ((lid & 7) + (lid >> 4) * 8) * ROWB + ((lid >> 3) & 1) * 16;
        const uint32_t Abase = smem_base + AG_A + offA;
        const uint32_t Bbase = smem_base + AG_B + wid * 16 * ROWB + offB;

        float acc[4][2][4];
        #pragma unroll
        for (int mb = 0; mb < 4; mb++)
            #pragma unroll
            for (int nt = 0; nt < 2; nt++)
                #pragma unroll
                for (int q = 0; q < 4; q++) acc[mb][nt][q] = 0.f;

        #pragma unroll
        for (int ks = 0; ks < 8; ks++) {
            const int kB = ks * 32;
            uint32_t b[4];
            ldsm4(b, Bbase + kB);
            #pragma unroll
            for (int mb = 0; mb < 4; mb++) {
                uint32_t a[4];
                ldsm4(a, Abase + mb * 16 * ROWB + kB);
                mma16816h(acc[mb][0], a, &b[0]);
                mma16816h(acc[mb][1], a, &b[2]);
            }
        }

        // scatter Yt fragments to smem in σ storage layout:
        // logical col = 16w + nt*8 + 2tig + e  ->  storage col = 64(w>>2) + tig*16 + ((2w+nt)&7)*2 + e
        unsigned char* Yts = smem + AG_YT;
        #pragma unroll
        for (int nt = 0; nt < 2; nt++) {
            int scol = 64 * (wid >> 2) + tig * 16 + (((2 * wid + nt) & 7)) * 2;
            #pragma unroll
            for (int mb = 0; mb < 4; mb++) {
                int r0 = mb * 16 + g;
                *(uint32_t*)(Yts + r0 * 256 + scol * 2) =
                    h2bits(__floats2half2_rn(acc[mb][nt][0], acc[mb][nt][1]));
                *(uint32_t*)(Yts + (r0 + 8) * 256 + scol * 2) =
                    h2bits(__floats2half2_rn(acc[mb][nt][2], acc[mb][nt][3]));
            }
        }
    }

    pdl_wait();      // Yb ready
    __syncthreads(); // Yt smem complete

    // ---- phase 2: gather-mean, 8 nodes per warp (pairs of 2, half-warp split) ----
    const int c = lid & 15, h = lid >> 4;
    const unsigned char* Yts = smem + AG_YT;
    #pragma unroll
    for (int p = 0; p < 4; p++) {
        int l0 = wid * 8 + p * 2;          // local rows
        int node0 = base + l0, node1 = node0 + 1;
        if (node0 >= N) break;
        bool has1 = node1 < N;
        const int* nb0 = nbr + (size_t)node0 * DEG;
        const int* nb1 = nbr + (size_t)(has1 ? node1 : node0) * DEG;
        int idxA[8], idxB[8];
        #pragma unroll
        for (int d = 0; d < 8; d++) {
            idxA[d] = __ldg(nb0 + 2 * d + h);
            idxB[d] = __ldg(nb1 + 2 * d + h);
        }
        float a0[8], a1[8];
        #pragma unroll
        for (int q = 0; q < 8; q++) { a0[q] = 0.f; a1[q] = 0.f; }
        #pragma unroll
        for (int d = 0; d < 8; d++) {
            uint4 uA = *(const uint4*)(Yb + (size_t)idxA[d] * 128 + c * 8);
            uint4 uB = *(const uint4*)(Yb + (size_t)idxB[d] * 128 + c * 8);
            acc8(a0, uA);
            acc8(a1, uB);
        }
        #pragma unroll
        for (int q = 0; q < 8; q++) {
            a0[q] += __shfl_xor_sync(0xFFFFFFFFu, a0[q], 16);
            a1[q] += __shfl_xor_sync(0xFFFFFFFFu, a1[q], 16);
        }
        int mynode = h ? node1 : node0;
        int myloc  = h ? (l0 + 1) : l0;
        float* ma = h ? a1 : a0;
        if (mynode < N) {
            uint4 t = *(const uint4*)(Yts + myloc * 256 + c * 16);
            float2 t0 = __half22float2(*reinterpret_cast<__half2*>(&t.x));
            float2 t1 = __half22float2(*reinterpret_cast<__half2*>(&t.y));
            float2 t2 = __half22float2(*reinterpret_cast<__half2*>(&t.z));
            float2 t3 = __half22float2(*reinterpret_cast<__half2*>(&t.w));
            uint4 o;
            o.x = h2bits(__floats2half2_rn(t0.x + ma[0] * 0.0625f, t0.y + ma[1] * 0.0625f));
            o.y = h2bits(__floats2half2_rn(t1.x + ma[2] * 0.0625f, t1.y + ma[3] * 0.0625f));
            o.z = h2bits(__floats2half2_rn(t2.x + ma[4] * 0.0625f, t2.y + ma[5] * 0.0625f));
            o.w = h2bits(__floats2half2_rn(t3.x + ma[6] * 0.0625f, t3.y + ma[7] * 0.0625f));
            *(uint4*)(h1 + (size_t)mynode * 128 + c * 8) = o;
        }
    }
    pdl_trigger();
}

// ---------------- kernel 4: agg2  x2[b] = [h1[nodes[b]], f16(mean(h1[nbr]))] ----------------
__global__ void __launch_bounds__(256) agg2_kernel(
    const __half* __restrict__ h1, const int* __restrict__ nbr,
    const int* __restrict__ nodes, __half* __restrict__ x2, int B)
{
    int wid = threadIdx.x >> 5, lid = threadIdx.x & 31;
    int c = lid & 15, h = lid >> 4;
    int b = blockIdx.x * 8 + wid;
    if (b >= B) { pdl_wait(); pdl_trigger(); return; }
    int self = __ldg(nodes + b);
    const int* nb = nbr + (size_t)self * DEG;
    int idx[8];
    #pragma unroll
    for (int d = 0; d < 8; d++) idx[d] = __ldg(nb + 2 * d + h);

    pdl_wait();   // h1 ready

    float a[8];
    #pragma unroll
    for (int q = 0; q < 8; q++) a[q] = 0.f;
    #pragma unroll
    for (int d = 0; d < 8; d++) {
        uint4 u = *(const uint4*)(h1 + (size_t)idx[d] * 128 + c * 8);
        acc8(a, u);
    }
    #pragma unroll
    for (int q = 0; q < 8; q++)
        a[q] += __shfl_xor_sync(0xFFFFFFFFu, a[q], 16);

    size_t base = (size_t)b * 256;
    if (h == 0) {
        uint4 sv = *(const uint4*)(h1 + (size_t)self * 128 + c * 8);
        *(uint4*)(x2 + base + c * 8) = sv;
    } else {
        uint4 o;
        o.x = h2bits(__floats2half2_rn(a[0] * 0.0625f, a[1] * 0.0625f));
        o.y = h2bits(__floats2half2_rn(a[2] * 0.0625f, a[3] * 0.0625f));
        o.z = h2bits(__floats2half2_rn(a[4] * 0.0625f, a[5] * 0.0625f));
        o.w = h2bits(__floats2half2_rn(a[6] * 0.0625f, a[7] * 0.0625f));
        *(uint4*)(x2 + base + 128 + c * 8) = o;
    }
    pdl_trigger();
}

// ---------------- kernel 5: gemm2  out[B,128] = x2[B,256] @ (w2h + w2l) ----------------
__global__ void __launch_bounds__(256, 1) gemm2_kernel(
    const __half* __restrict__ x2, float* __restrict__ out, int B)
{
    extern __shared__ unsigned char smem[];
    const int tid = threadIdx.x, wid = tid >> 5, lid = tid & 31;
    const int g   = lid >> 2, tig = lid & 3;
    const int warp_m = wid & 1, warp_n = wid >> 1;
    const uint32_t smem_base = smem_u32(smem);
    const int base = blockIdx.x * 64;

    const int offA = ((lid & 7) + ((lid >> 3) & 1) * 8) * ROWB2 + (lid >> 4) * 16;
    const int offB = ((lid & 7) + (lid >> 4) * 8) * ROWB2 + ((lid >> 3) & 1) * 16;

    {
        const uint4* src = (const uint4*)&g_B2img[0][0];
        uint4* dst = (uint4*)(smem + A2SLAB);
        #pragma unroll 4
        for (int i = tid; i < 2 * B2SLAB / 16; i += 256) dst[i] = src[i];
    }

    pdl_wait();   // x2 ready

    {
        int r = tid >> 2, q = tid & 3;
        int grow = base + r;
        const uint4* sh = (const uint4*)(x2 + (size_t)grow * 256) + q * 8;
        uint4* dh = (uint4*)(smem + r * ROWB2 + q * 128);
        if (grow < B) {
            #pragma unroll
            for (int j = 0; j < 8; j++) dh[j] = sh[j];
        } else {
            uint4 z = make_uint4(0, 0, 0, 0);
            #pragma unroll
            for (int j = 0; j < 8; j++) dh[j] = z;
        }
    }
    __syncthreads();

    float acc[2][4][4];
    #pragma unroll
    for (int mb = 0; mb < 2; mb++)
        #pragma unroll
        for (int nb = 0; nb < 4; nb++)
            #pragma unroll
            for (int q = 0; q < 4; q++) acc[mb][nb][q] = 0.f;

    #pragma unroll
    for (int p = 0; p < 2; p++) {
        const uint32_t Abase = smem_base + warp_m * 32 * ROWB2 + offA;
        const uint32_t Bbase = smem_base + A2SLAB + p * B2SLAB
                             + warp_n * 32 * ROWB2 + offB;
        #pragma unroll
        for (int ks = 0; ks < 16; ks++) {
            const int kB = ks * 32;
            uint32_t a[2][4];
            ldsm4(a[0], Abase + kB);
            ldsm4(a[1], Abase + 16 * ROWB2 + kB);
            uint32_t b[2][4];
            ldsm4(b[0], Bbase + kB);
            ldsm4(b[1], Bbase + 16 * ROWB2 + kB);
            #pragma unroll
            for (int mb = 0; mb < 2; mb++)
                #pragma unroll
                for (int pr = 0; pr < 2; pr++) {
                    mma16816h(acc[mb][pr * 2],     a[mb], &b[pr][0]);
                    mma16816h(acc[mb][pr * 2 + 1], a[mb], &b[pr][2]);
                }
        }
    }

    #pragma unroll
    for (int mb = 0; mb < 2; mb++) {
        int row0 = base + warp_m * 32 + mb * 16 + g;
        #pragma unroll
        for (int nb = 0; nb < 4; nb++) {
            int col = warp_n * 32 + nb * 8 + tig * 2;
            if (row0 < B)
                *(float2*)(out + (size_t)row0 * 128 + col) =
                    make_float2(acc[mb][nb][0], acc[mb][nb][1]);
            if (row0 + 8 < B)
                *(float2*)(out + (size_t)(row0 + 8) * 128 + col) =
                    make_float2(acc[mb][nb][2], acc[mb][nb][3]);
        }
    }
}

// ---------------- host ----------------
static void launch_pdl(void* fn, dim3 grid, dim3 block, size_t smem, void** args) {
    cudaLaunchConfig_t cfg = {};
    cfg.gridDim = grid;
    cfg.blockDim = block;
    cfg.dynamicSmemBytes = smem;
    cfg.stream = 0;
    cudaLaunchAttribute attr[1];
    attr[0].id = cudaLaunchAttributeProgrammaticStreamSerialization;
    attr[0].val.programmaticStreamSerializationAllowed = 1;
    cfg.attrs = attr;
    cfg.numAttrs = 1;
    cudaLaunchKernelExC(&cfg, fn, args);
}

extern "C" void kernel_launch(void* const* d_in, const int* in_sizes, int n_in,
                              void* d_out, int out_size)
{
    const float* features     = (const float*)d_in[0];
    const float* w1           = (const float*)d_in[1];
    const float* w2           = (const float*)d_in[2];
    const int*   neighbor_idx = (const int*)d_in[3];
    const int*   nodes        = (const int*)d_in[4];
    float*       out          = (float*)d_out;

    const int N = in_sizes[0] / F;
    const int B = in_sizes[4];

    __half *Yb, *h1p, *x2;
    cudaGetSymbolAddress((void**)&Yb,  g_Yb);
    cudaGetSymbolAddress((void**)&h1p, g_h1);
    cudaGetSymbolAddress((void**)&x2,  g_x2);

    cudaFuncSetAttribute(gemm1b_kernel, cudaFuncAttributeMaxDynamicSharedMemorySize, SMEM_G1);
    cudaFuncSetAttribute(agg1f_kernel,  cudaFuncAttributeMaxDynamicSharedMemorySize, SMEM_AG);
    cudaFuncSetAttribute(gemm2_kernel,  cudaFuncAttributeMaxDynamicSharedMemorySize, SMEM_G2);

    // 1) weight images (root)
    prep_kernel<<<256, 256>>>(w1, w2);

    // 2) gemm1b: Yb only
    int nHT = (N + 63) / 64;
    {
        void* args[] = { (void*)&features, (void*)&Yb, (void*)&N, (void*)&nHT };
        launch_pdl((void*)gemm1b_kernel, dim3(296), dim3(256), SMEM_G1, args);
    }
    // 3) agg1f: fused Yt-GEMM + gather-mean -> h1
    {
        int grid = (N + 63) / 64;
        void* args[] = { (void*)&features, (void*)&Yb, (void*)&neighbor_idx, (void*)&h1p, (void*)&N };
        launch_pdl((void*)agg1f_kernel, dim3(grid), dim3(256), SMEM_AG, args);
    }
    // 4) agg2
    {
        int grid = (B + 7) / 8;
        void* args[] = { (void*)&h1p, (void*)&neighbor_idx, (void*)&nodes, (void*)&x2, (void*)&B };
        launch_pdl((void*)agg2_kernel, dim3(grid), dim3(256), 0, args);
    }
    // 5) gemm2
    {
        int grid = (B + 63) / 64;
        void* args[] = { (void*)&x2, (void*)&out, (void*)&B };
        launch_pdl((void*)gemm2_kernel, dim3(grid), dim3(256), SMEM_G2, args);
    }
}

// round 16
// speedup vs baseline: 1.2120x; 1.2120x over previous
#include <cuda_runtime.h>
#include <cuda_bf16.h>
#include <cuda_fp16.h>
#include <cstdint>

#define F      128
#define H      128
#define DEG    16
#define KDIM   256
#define NMAX   131072
#define BMAX   16384
#define PITCH  136            // fp16/row gemm1 (K=128); 272 B ≡ 4 words (mod 32) -> conflict-free
#define ROWB   272
#define HSLAB  (64 * ROWB)    // 17408 B  (64-row A half-slab)
#define SLAB   (128 * ROWB)   // 34816 B  (128-n B slab)
#define ABUF_T (2 * HSLAB)    // 34816 B  (A: 2 buffers)
#define SMEM_G1 (ABUF_T + 2 * SLAB)   // 104448 B -> 2 CTAs/SM

#define PITCH2 264            // fp16/row gemm2 (K=256); 528 B ≡ 4 words (mod 32)
#define ROWB2  528
#define A2SLAB (64 * ROWB2)   // 33792 B
#define B2SLAB (128 * ROWB2)  // 67584 B (single level)
#define SMEM_G2 (A2SLAB + B2SLAB)     // 101376 B

// ---------------- scratch (all intermediates fp16; Yt/Yb/h1/x2 in PERMUTED col layout) ----
__device__ __half g_Yt[(size_t)NMAX * 128];     // f @ w1_top  (streamed, evict-first)
__device__ __half g_Yb[(size_t)NMAX * 128];     // f @ w1_bot  (gathered)
__device__ __half g_h1[(size_t)NMAX * 128];     // layer-1 embeddings
__device__ __half g_B1img[2][128 * PITCH];      // [ch][n][k]   (w1 fp16)
__device__ __half g_B2img[128 * PITCH2];        // [n][p]       (w2 fp16, k-rows permuted)
__device__ __half g_x2[(size_t)BMAX * 256];     // layer2 input (fp16)

// ---------------- PTX helpers ----------------
__device__ __forceinline__ void mma16816h(float* c, const uint32_t* a, const uint32_t* b) {
    asm volatile(
        "mma.sync.aligned.m16n8k16.row.col.f32.f16.f16.f32 "
        "{%0,%1,%2,%3}, {%4,%5,%6,%7}, {%8,%9}, {%0,%1,%2,%3};"
        : "+f"(c[0]), "+f"(c[1]), "+f"(c[2]), "+f"(c[3])
        : "r"(a[0]), "r"(a[1]), "r"(a[2]), "r"(a[3]), "r"(b[0]), "r"(b[1]));
}
__device__ __forceinline__ void ldsm4(uint32_t* r, uint32_t addr) {
    asm volatile("ldmatrix.sync.aligned.m8n8.x4.shared.b16 {%0,%1,%2,%3}, [%4];"
        : "=r"(r[0]), "=r"(r[1]), "=r"(r[2]), "=r"(r[3]) : "r"(addr));
}
__device__ __forceinline__ uint32_t smem_u32(const void* p) {
    return (uint32_t)__cvta_generic_to_shared(p);
}
__device__ __forceinline__ uint32_t h2bits(__half2 h) {
    return *reinterpret_cast<uint32_t*>(&h);
}
// PDL intrinsics (griddepcontrol; sm_90+ base ISA)
__device__ __forceinline__ void pdl_wait() {
    asm volatile("griddepcontrol.wait;" ::: "memory");
}
__device__ __forceinline__ void pdl_trigger() {
    asm volatile("griddepcontrol.launch_dependents;" :::);
}
// accumulate 8 fp16 (uint4) into 8 fp32
__device__ __forceinline__ void acc8(float* a, uint4 u) {
    float2 p0 = __half22float2(*reinterpret_cast<__half2*>(&u.x));
    float2 p1 = __half22float2(*reinterpret_cast<__half2*>(&u.y));
    float2 p2 = __half22float2(*reinterpret_cast<__half2*>(&u.z));
    float2 p3 = __half22float2(*reinterpret_cast<__half2*>(&u.w));
    a[0] += p0.x; a[1] += p0.y; a[2] += p1.x; a[3] += p1.y;
    a[4] += p2.x; a[5] += p2.y; a[6] += p3.x; a[7] += p3.y;
}

// ---------------- kernel 1: build fp16 weight images ----------------
// w1: B1img[ch][n][k] = f16(w1[ch*128+k][n])
// w2: B2img[n][p] = f16(w2[sigma2(p)][n]) with
//     sigma(p127) = (p127&64) + ((p127>>1)&7)*8 + ((p127>>4)&3)*2 + (p127&1)
__global__ void prep_kernel(const float* __restrict__ w1, const float* __restrict__ w2) {
    int i = blockIdx.x * 256 + threadIdx.x;          // 65536 total
    if (i < 32768) {
        int ch = i >> 14, n = (i >> 7) & 127, k = i & 127;
        float v = w1[(size_t)(ch * 128 + k) * 128 + n];
        g_B1img[ch][n * PITCH + k] = __float2half_rn(v);
    } else if (i < 65536) {
        int j = i - 32768;
        int n = j & 127, p = j >> 7;                 // p = storage k-index 0..255
        int p1  = p & 127;
        int sig = (p1 & 64) + ((p1 >> 1) & 7) * 8 + ((p1 >> 4) & 3) * 2 + (p1 & 1);
        int k   = (p & 128) + sig;
        g_B2img[n * PITCH2 + p] = __float2half_rn(w2[(size_t)k * 128 + n]);
    }
    pdl_trigger();
}

// ---------------- kernel 2: gemm1  Y[N,256] = f16(f)[N,128] @ f16(w1) ----------------
// Outputs stored fp16 in permuted col layout: storage col = (chunk64) + tig*16 + nb*2 + e.
// smem: A[buf2] @ buf*HSLAB ; B[ch2] @ ABUF_T + ch*SLAB
__global__ void __launch_bounds__(256, 2) gemm1_kernel(
    const float* __restrict__ f, __half* __restrict__ Yt, __half* __restrict__ Yb,
    int nRows, int nHT)
{
    extern __shared__ unsigned char smem[];
    const int tid = threadIdx.x, wid = tid >> 5, lid = tid & 31;
    const int g   = lid >> 2, tig = lid & 3;
    const int warp_m = wid & 1, warp_n = wid >> 1;       // 2 x 32 rows, 4 x 64 cols
    const int chn = warp_n >> 1, ncl = (warp_n & 1) * 64;
    const uint32_t smem_base = smem_u32(smem);

    const int offA = ((lid & 7) + ((lid >> 3) & 1) * 8) * ROWB + (lid >> 4) * 16;
    const int offB = ((lid & 7) + (lid >> 4) * 8) * ROWB + ((lid >> 3) & 1) * 16;

    const int r_st = tid >> 5;          // row in 8-row group
    const int k_st = (tid & 31) * 4;    // k0 elements

    float4 Rst[8];
    auto LOADHT = [&](int ht) {
        const int base = ht * 64;
        #pragma unroll
        for (int j = 0; j < 8; j++) {
            int grow = base + j * 8 + r_st;
            Rst[j] = (grow < nRows) ? *(const float4*)(f + (size_t)grow * 128 + k_st)
                                    : make_float4(0.f, 0.f, 0.f, 0.f);
        }
    };
    auto STOREHT = [&](int buf) {
        unsigned char* Ah = smem + buf * HSLAB;
        #pragma unroll
        for (int j = 0; j < 8; j++) {
            uint2 u;
            u.x = h2bits(__floats2half2_rn(Rst[j].x, Rst[j].y));
            u.y = h2bits(__floats2half2_rn(Rst[j].z, Rst[j].w));
            int r = j * 8 + r_st;
            *(uint2*)(Ah + r * ROWB + k_st * 2) = u;
        }
    };

    // Prologue independent of prep: load first A tile from f.
    int cur = 0;
    int ht = blockIdx.x;
    if (ht < nHT) { LOADHT(ht); STOREHT(0); }

    // Wait for prep's B1img, then stage both B slabs.
    pdl_wait();
    {
        const uint4* src = (const uint4*)&g_B1img[0][0];
        uint4* dst = (uint4*)(smem + ABUF_T);
        #pragma unroll 4
        for (int i = tid; i < 2 * SLAB / 16; i += 256) dst[i] = src[i];
    }
    __syncthreads();

    while (ht < nHT) {
        const int htn  = ht + gridDim.x;
        const int base = ht * 64;

        if (htn < nHT) LOADHT(htn);

        float acc[2][8][4];
        #pragma unroll
        for (int mb = 0; mb < 2; mb++)
            #pragma unroll
            for (int nb = 0; nb < 8; nb++)
                #pragma unroll
                for (int q = 0; q < 4; q++) acc[mb][nb][q] = 0.f;

        const uint32_t Abase = smem_base + cur * HSLAB + warp_m * 32 * ROWB + offA;
        const uint32_t Bbase = smem_base + ABUF_T + chn * SLAB + ncl * ROWB + offB;
        #pragma unroll
        for (int ks = 0; ks < 8; ks++) {
            const int kB = ks * 32;
            uint32_t a[2][4];
            ldsm4(a[0], Abase + kB);
            ldsm4(a[1], Abase + 16 * ROWB + kB);
            uint32_t b[4][4];
            #pragma unroll
            for (int pr = 0; pr < 4; pr++)
                ldsm4(b[pr], Bbase + pr * 16 * ROWB + kB);
            #pragma unroll
            for (int mb = 0; mb < 2; mb++)
                #pragma unroll
                for (int pr = 0; pr < 4; pr++) {
                    mma16816h(acc[mb][pr * 2],     a[mb], &b[pr][0]);
                    mma16816h(acc[mb][pr * 2 + 1], a[mb], &b[pr][2]);
                }
        }

        // permuted epilogue: 16 contiguous halfs per (thread, row) -> 2x STG.128
        __half* dst = (chn == 0) ? Yt : Yb;
        const bool stream = (chn == 0);
        const int colp = (warp_n & 1) * 64 + tig * 16;
        #pragma unroll
        for (int mb = 0; mb < 2; mb++) {
            int row0 = base + warp_m * 32 + mb * 16 + g;
            #pragma unroll
            for (int half = 0; half < 2; half++) {
                int r = row0 + half * 8;
                if (r < nRows) {
                    uint4 v0 = make_uint4(
                        h2bits(__floats2half2_rn(acc[mb][0][half*2], acc[mb][0][half*2+1])),
                        h2bits(__floats2half2_rn(acc[mb][1][half*2], acc[mb][1][half*2+1])),
                        h2bits(__floats2half2_rn(acc[mb][2][half*2], acc[mb][2][half*2+1])),
                        h2bits(__floats2half2_rn(acc[mb][3][half*2], acc[mb][3][half*2+1])));
                    uint4 v1 = make_uint4(
                        h2bits(__floats2half2_rn(acc[mb][4][half*2], acc[mb][4][half*2+1])),
                        h2bits(__floats2half2_rn(acc[mb][5][half*2], acc[mb][5][half*2+1])),
                        h2bits(__floats2half2_rn(acc[mb][6][half*2], acc[mb][6][half*2+1])),
                        h2bits(__floats2half2_rn(acc[mb][7][half*2], acc[mb][7][half*2+1])));
                    uint4* p0 = (uint4*)(dst + (size_t)r * 128 + colp);
                    if (stream) { __stcs(p0, v0); __stcs(p0 + 1, v1); }
                    else        { p0[0] = v0;     p0[1] = v1; }
                }
            }
        }

        if (htn < nHT) STOREHT(cur ^ 1);
        __syncthreads();
        cur ^= 1;
        ht = htn;
    }
    pdl_trigger();
}

// ---------------- kernel 3: agg1  h1[i] = f16(Yt[i] + mean_d Yb[nbr[i][d]]) ----------------
// 2 nodes per warp; half-warp h gathers neighbor subset {2d+h}; uint4 (16B) loads;
// shfl_xor(16) combines halves; each half then finalizes one node in parallel.
__global__ void __launch_bounds__(256) agg1_kernel(
    const __half* __restrict__ Yt, const __half* __restrict__ Yb,
    const int* __restrict__ nbr, __half* __restrict__ h1, int N)
{
    int wid = threadIdx.x >> 5, lid = threadIdx.x & 31;
    int c = lid & 15, h = lid >> 4;
    int node0 = (blockIdx.x * 8 + wid) * 2;
    if (node0 >= N) { pdl_wait(); pdl_trigger(); return; }
    int node1 = node0 + 1;
    bool has1 = node1 < N;

    // prologue independent of gemm1: neighbor indices (h-th subset of each node)
    const int* nb0 = nbr + (size_t)node0 * DEG;
    const int* nb1 = nbr + (size_t)(has1 ? node1 : node0) * DEG;
    int idxA[8], idxB[8];
    #pragma unroll
    for (int d = 0; d < 8; d++) {
        idxA[d] = __ldg(nb0 + 2 * d + h);
        idxB[d] = __ldg(nb1 + 2 * d + h);
    }

    pdl_wait();   // Yt/Yb ready

    float a0[8], a1[8];
    #pragma unroll
    for (int q = 0; q < 8; q++) { a0[q] = 0.f; a1[q] = 0.f; }
    #pragma unroll
    for (int d = 0; d < 8; d++) {
        uint4 uA = *(const uint4*)(Yb + (size_t)idxA[d] * 128 + c * 8);
        uint4 uB = *(const uint4*)(Yb + (size_t)idxB[d] * 128 + c * 8);
        acc8(a0, uA);
        acc8(a1, uB);
    }
    // combine the two halves' partial sums
    #pragma unroll
    for (int q = 0; q < 8; q++) {
        a0[q] += __shfl_xor_sync(0xFFFFFFFFu, a0[q], 16);
        a1[q] += __shfl_xor_sync(0xFFFFFFFFu, a1[q], 16);
    }
    // half 0 finalizes node0, half 1 finalizes node1 (both have full sums)
    int mynode = h ? node1 : node0;
    float* ma = h ? a1 : a0;
    if (mynode < N) {
        uint4 t = __ldcs((const uint4*)(Yt + (size_t)mynode * 128 + c * 8));
        float2 t0 = __half22float2(*reinterpret_cast<__half2*>(&t.x));
        float2 t1 = __half22float2(*reinterpret_cast<__half2*>(&t.y));
        float2 t2 = __half22float2(*reinterpret_cast<__half2*>(&t.z));
        float2 t3 = __half22float2(*reinterpret_cast<__half2*>(&t.w));
        uint4 o;
        o.x = h2bits(__floats2half2_rn(t0.x + ma[0] * 0.0625f, t0.y + ma[1] * 0.0625f));
        o.y = h2bits(__floats2half2_rn(t1.x + ma[2] * 0.0625f, t1.y + ma[3] * 0.0625f));
        o.z = h2bits(__floats2half2_rn(t2.x + ma[4] * 0.0625f, t2.y + ma[5] * 0.0625f));
        o.w = h2bits(__floats2half2_rn(t3.x + ma[6] * 0.0625f, t3.y + ma[7] * 0.0625f));
        *(uint4*)(h1 + (size_t)mynode * 128 + c * 8) = o;
    }
    pdl_trigger();
}

// ---------------- kernel 4: agg2  x2[b] = [h1[nodes[b]], f16(mean(h1[nbr]))] ----------------
// 1 row per warp; half-warp split over neighbors; uint4 loads; shfl combine.
__global__ void __launch_bounds__(256) agg2_kernel(
    const __half* __restrict__ h1, const int* __restrict__ nbr,
    const int* __restrict__ nodes, __half* __restrict__ x2, int B)
{
    int wid = threadIdx.x >> 5, lid = threadIdx.x & 31;
    int c = lid & 15, h = lid >> 4;
    int b = blockIdx.x * 8 + wid;
    if (b >= B) { pdl_wait(); pdl_trigger(); return; }
    // prologue independent of agg1: self + neighbor indices
    int self = __ldg(nodes + b);
    const int* nb = nbr + (size_t)self * DEG;
    int idx[8];
    #pragma unroll
    for (int d = 0; d < 8; d++) idx[d] = __ldg(nb + 2 * d + h);

    pdl_wait();   // h1 ready

    float a[8];
    #pragma unroll
    for (int q = 0; q < 8; q++) a[q] = 0.f;
    #pragma unroll
    for (int d = 0; d < 8; d++) {
        uint4 u = *(const uint4*)(h1 + (size_t)idx[d] * 128 + c * 8);
        acc8(a, u);
    }
    #pragma unroll
    for (int q = 0; q < 8; q++)
        a[q] += __shfl_xor_sync(0xFFFFFFFFu, a[q], 16);

    size_t base = (size_t)b * 256;
    if (h == 0) {
        // self half: straight fp16 bit-copy (16 lanes x 16B = 256B)
        uint4 sv = *(const uint4*)(h1 + (size_t)self * 128 + c * 8);
        *(uint4*)(x2 + base + c * 8) = sv;
    } else {
        // mean half
        uint4 o;
        o.x = h2bits(__floats2half2_rn(a[0] * 0.0625f, a[1] * 0.0625f));
        o.y = h2bits(__floats2half2_rn(a[2] * 0.0625f, a[3] * 0.0625f));
        o.z = h2bits(__floats2half2_rn(a[4] * 0.0625f, a[5] * 0.0625f));
        o.w = h2bits(__floats2half2_rn(a[6] * 0.0625f, a[7] * 0.0625f));
        *(uint4*)(x2 + base + 128 + c * 8) = o;
    }
    pdl_trigger();
}

// ---------------- kernel 5: gemm2  out[B,128] = x2[B,256] @ f16(w2) (single level) ----------------
// smem: A @ 0 ; B @ A2SLAB
__global__ void __launch_bounds__(256, 1) gemm2_kernel(
    const __half* __restrict__ x2, float* __restrict__ out, int B)
{
    extern __shared__ unsigned char smem[];
    const int tid = threadIdx.x, wid = tid >> 5, lid = tid & 31;
    const int g   = lid >> 2, tig = lid & 3;
    const int warp_m = wid & 1, warp_n = wid >> 1;   // 2 x 32 rows, 4 x 32 cols
    const uint32_t smem_base = smem_u32(smem);
    const int base = blockIdx.x * 64;

    const int offA = ((lid & 7) + ((lid >> 3) & 1) * 8) * ROWB2 + (lid >> 4) * 16;
    const int offB = ((lid & 7) + (lid >> 4) * 8) * ROWB2 + ((lid >> 3) & 1) * 16;

    // prologue independent of agg2: stage B (prep output) — overlaps agg2's tail
    {
        const uint4* src = (const uint4*)&g_B2img[0];
        uint4* dst = (uint4*)(smem + A2SLAB);
        #pragma unroll 4
        for (int i = tid; i < B2SLAB / 16; i += 256) dst[i] = src[i];
    }

    pdl_wait();   // x2 ready

    // stage A: 64 rows x 512B, pitched to 528
    {
        int r = tid >> 2, q = tid & 3;               // r 0..63, 128B quarter
        int grow = base + r;
        const uint4* sh = (const uint4*)(x2 + (size_t)grow * 256) + q * 8;
        uint4* dh = (uint4*)(smem + r * ROWB2 + q * 128);
        if (grow < B) {
            #pragma unroll
            for (int j = 0; j < 8; j++) dh[j] = sh[j];
        } else {
            uint4 z = make_uint4(0, 0, 0, 0);
            #pragma unroll
            for (int j = 0; j < 8; j++) dh[j] = z;
        }
    }
    __syncthreads();

    float acc[2][4][4];
    #pragma unroll
    for (int mb = 0; mb < 2; mb++)
        #pragma unroll
        for (int nb = 0; nb < 4; nb++)
            #pragma unroll
            for (int q = 0; q < 4; q++) acc[mb][nb][q] = 0.f;

    {
        const uint32_t Abase = smem_base + warp_m * 32 * ROWB2 + offA;
        const uint32_t Bbase = smem_base + A2SLAB + warp_n * 32 * ROWB2 + offB;
        #pragma unroll
        for (int ks = 0; ks < 16; ks++) {
            const int kB = ks * 32;
            uint32_t a[2][4];
            ldsm4(a[0], Abase + kB);
            ldsm4(a[1], Abase + 16 * ROWB2 + kB);
            uint32_t b[2][4];
            ldsm4(b[0], Bbase + kB);
            ldsm4(b[1], Bbase + 16 * ROWB2 + kB);
            #pragma unroll
            for (int mb = 0; mb < 2; mb++)
                #pragma unroll
                for (int pr = 0; pr < 2; pr++) {
                    mma16816h(acc[mb][pr * 2],     a[mb], &b[pr][0]);
                    mma16816h(acc[mb][pr * 2 + 1], a[mb], &b[pr][2]);
                }
        }
    }

    #pragma unroll
    for (int mb = 0; mb < 2; mb++) {
        int row0 = base + warp_m * 32 + mb * 16 + g;
        #pragma unroll
        for (int nb = 0; nb < 4; nb++) {
            int col = warp_n * 32 + nb * 8 + tig * 2;
            if (row0 < B)
                *(float2*)(out + (size_t)row0 * 128 + col) =
                    make_float2(acc[mb][nb][0], acc[mb][nb][1]);
            if (row0 + 8 < B)
                *(float2*)(out + (size_t)(row0 + 8) * 128 + col) =
                    make_float2(acc[mb][nb][2], acc[mb][nb][3]);
        }
    }
}

// ---------------- host ----------------
static void launch_pdl(void* fn, dim3 grid, dim3 block, size_t smem, void** args) {
    cudaLaunchConfig_t cfg = {};
    cfg.gridDim = grid;
    cfg.blockDim = block;
    cfg.dynamicSmemBytes = smem;
    cfg.stream = 0;
    cudaLaunchAttribute attr[1];
    attr[0].id = cudaLaunchAttributeProgrammaticStreamSerialization;
    attr[0].val.programmaticStreamSerializationAllowed = 1;
    cfg.attrs = attr;
    cfg.numAttrs = 1;
    cudaLaunchKernelExC(&cfg, fn, args);
}

extern "C" void kernel_launch(void* const* d_in, const int* in_sizes, int n_in,
                              void* d_out, int out_size)
{
    const float* features     = (const float*)d_in[0];
    const float* w1           = (const float*)d_in[1];
    const float* w2           = (const float*)d_in[2];
    const int*   neighbor_idx = (const int*)d_in[3];
    const int*   nodes        = (const int*)d_in[4];
    float*       out          = (float*)d_out;

    const int N = in_sizes[0] / F;
    const int B = in_sizes[4];

    __half *Yt, *Yb, *h1p, *x2;
    cudaGetSymbolAddress((void**)&Yt,  g_Yt);
    cudaGetSymbolAddress((void**)&Yb,  g_Yb);
    cudaGetSymbolAddress((void**)&h1p, g_h1);
    cudaGetSymbolAddress((void**)&x2,  g_x2);

    cudaFuncSetAttribute(gemm1_kernel, cudaFuncAttributeMaxDynamicSharedMemorySize, SMEM_G1);
    cudaFuncSetAttribute(gemm2_kernel, cudaFuncAttributeMaxDynamicSharedMemorySize, SMEM_G2);

    // 1) weight images (no PDL attr; it is the root)
    prep_kernel<<<256, 256>>>(w1, w2);

    // 2) gemm1 (PDL: overlaps its A-tile prologue with prep)
    int nHT = (N + 63) / 64;
    {
        void* args[] = { (void*)&features, (void*)&Yt, (void*)&Yb, (void*)&N, (void*)&nHT };
        launch_pdl((void*)gemm1_kernel, dim3(296), dim3(256), SMEM_G1, args);
    }
    // 3) agg1 (PDL; 2 nodes/warp)
    {
        int grid = (N + 15) / 16;
        void* args[] = { (void*)&Yt, (void*)&Yb, (void*)&neighbor_idx, (void*)&h1p, (void*)&N };
        launch_pdl((void*)agg1_kernel, dim3(grid), dim3(256), 0, args);
    }
    // 4) agg2 (PDL)
    {
        int grid = (B + 7) / 8;
        void* args[] = { (void*)&h1p, (void*)&neighbor_idx, (void*)&nodes, (void*)&x2, (void*)&B };
        launch_pdl((void*)agg2_kernel, dim3(grid), dim3(256), 0, args);
    }
    // 5) gemm2 (PDL: B staging overlaps agg2)
    {
        int grid = (B + 63) / 64;
        void* args[] = { (void*)&x2, (void*)&out, (void*)&B };
        launch_pdl((void*)gemm2_kernel, dim3(grid), dim3(256), SMEM_G2, args);
    }
}